// round 4
// baseline (speedup 1.0000x reference)
#include <cuda_runtime.h>
#include <math.h>
#include <stdint.h>

// Problem constants (fixed by the dataset)
#define K_IN    768
#define C_OUT   64
#define N_PAPER 150000
#define E_MAX   1500000

// ---------------------------------------------------------------------------
// Scratch (device globals; allocation is forbidden)
// ---------------------------------------------------------------------------
__device__ __align__(16) float g_h[(size_t)N_PAPER * C_OUT];   // h_src of current edge type
__device__ __align__(16) float g_ssrc[N_PAPER];                // s_src of current edge type
__device__ __align__(16) float g_sdst[3 * N_PAPER];            // s_dst for all 3 types
__device__ __align__(16) float g_m[N_PAPER];                   // per-dst running max
__device__ __align__(16) float g_den[N_PAPER];                 // per-dst softmax denom
__device__ __align__(16) float g_ebuf[E_MAX];                  // per-edge e, then w
__device__ __align__(16) float g_v[3 * K_IN];                  // W_dst @ a_dst per type

// ---------------------------------------------------------------------------
// v_t = W_dst_t @ a_dst_t   (tiny: 3 x 768 x 64)
// ---------------------------------------------------------------------------
__global__ void compute_v_kernel(const float* __restrict__ W0, const float* __restrict__ a0,
                                 const float* __restrict__ W1, const float* __restrict__ a1,
                                 const float* __restrict__ W2, const float* __restrict__ a2) {
    int t = blockIdx.x;
    const float* W = (t == 0) ? W0 : (t == 1) ? W1 : W2;
    const float* a = (t == 0) ? a0 : (t == 1) ? a1 : a2;
    int j = threadIdx.x;  // 0..767
    float acc = 0.f;
#pragma unroll 8
    for (int c = 0; c < C_OUT; c++) acc = fmaf(W[j * C_OUT + c], a[c], acc);
    g_v[t * K_IN + j] = acc;
}

// ---------------------------------------------------------------------------
// out[i,c] = bw[c] + bc[c] + bp[c]   (biases of all 3 convs; sum aggregation)
// ---------------------------------------------------------------------------
__global__ void init_out_kernel(const float* __restrict__ bw, const float* __restrict__ bc,
                                const float* __restrict__ bp, float* __restrict__ out) {
    int idx = blockIdx.x * blockDim.x + threadIdx.x;
    if (idx < N_PAPER * C_OUT) {
        int c = idx & (C_OUT - 1);
        out[idx] = bw[c] + bc[c] + bp[c];
    }
}

__global__ void init_md_kernel() {
    int idx = blockIdx.x * blockDim.x + threadIdx.x;
    if (idx < N_PAPER) {
        g_m[idx] = -INFINITY;
        g_den[idx] = 0.f;
    }
}

// ---------------------------------------------------------------------------
// s_dst for all 3 types in one pass over x_paper: warp per row, 3 dots
// ---------------------------------------------------------------------------
__global__ void sdst_kernel(const float* __restrict__ X) {
    int warp = (blockIdx.x * blockDim.x + threadIdx.x) >> 5;
    int lane = threadIdx.x & 31;
    if (warp >= N_PAPER) return;
    const float4* xr = (const float4*)(X + (size_t)warp * K_IN);
    const float4* v0 = (const float4*)(g_v);
    const float4* v1 = (const float4*)(g_v + K_IN);
    const float4* v2 = (const float4*)(g_v + 2 * K_IN);
    float a0 = 0.f, a1 = 0.f, a2 = 0.f;
#pragma unroll
    for (int i = 0; i < (K_IN / 4) / 32; i++) {  // 6 iterations
        int k = i * 32 + lane;
        float4 x = xr[k];
        float4 u;
        u = v0[k]; a0 += x.x * u.x + x.y * u.y + x.z * u.z + x.w * u.w;
        u = v1[k]; a1 += x.x * u.x + x.y * u.y + x.z * u.z + x.w * u.w;
        u = v2[k]; a2 += x.x * u.x + x.y * u.y + x.z * u.z + x.w * u.w;
    }
#pragma unroll
    for (int o = 16; o; o >>= 1) {
        a0 += __shfl_xor_sync(0xffffffffu, a0, o);
        a1 += __shfl_xor_sync(0xffffffffu, a1, o);
        a2 += __shfl_xor_sync(0xffffffffu, a2, o);
    }
    if (lane == 0) {
        g_sdst[warp] = a0;
        g_sdst[N_PAPER + warp] = a1;
        g_sdst[2 * N_PAPER + warp] = a2;
    }
}

// ---------------------------------------------------------------------------
// GEMM: g_h[M x 64] = A[M x 768] @ B[768 x 64]   (fp32, smem-tiled)
// BM=128, BN=64, BK=16, 256 threads, 8x4 per thread
// ---------------------------------------------------------------------------
#define BM 128
#define BN 64
#define BK 16
__global__ __launch_bounds__(256) void gemm_kernel(const float* __restrict__ A,
                                                   const float* __restrict__ B, int M) {
    __shared__ float As[BK][BM];
    __shared__ float Bs[BK][BN];
    const int block_row = blockIdx.x * BM;
    const int tid = threadIdx.x;
    const int tx = tid & 15;  // col group: 4 cols
    const int ty = tid >> 4;  // row group: 8 rows

    float acc[8][4];
#pragma unroll
    for (int i = 0; i < 8; i++)
#pragma unroll
        for (int j = 0; j < 4; j++) acc[i][j] = 0.f;

    for (int k0 = 0; k0 < K_IN; k0 += BK) {
        // Load A tile (BM x BK) -> As transposed [BK][BM]; 2 float4 per thread
#pragma unroll
        for (int jj = 0; jj < 2; jj++) {
            int id = tid * 2 + jj;
            int r = id >> 2;            // 0..127
            int c4 = (id & 3) * 4;      // 0,4,8,12
            int gr = block_row + r;
            float4 v = (gr < M) ? *(const float4*)&A[(size_t)gr * K_IN + k0 + c4]
                                : make_float4(0.f, 0.f, 0.f, 0.f);
            As[c4 + 0][r] = v.x;
            As[c4 + 1][r] = v.y;
            As[c4 + 2][r] = v.z;
            As[c4 + 3][r] = v.w;
        }
        // Load B tile (BK x BN); 1 float4 per thread
        {
            int r = tid >> 4;           // 0..15
            int c4 = (tid & 15) * 4;    // 0..60
            *(float4*)&Bs[r][c4] = *(const float4*)&B[(size_t)(k0 + r) * BN + c4];
        }
        __syncthreads();

#pragma unroll
        for (int kk = 0; kk < BK; kk++) {
            float4 A0 = *(const float4*)&As[kk][ty * 8];
            float4 A1 = *(const float4*)&As[kk][ty * 8 + 4];
            float4 B0 = *(const float4*)&Bs[kk][tx * 4];
            float af[8] = {A0.x, A0.y, A0.z, A0.w, A1.x, A1.y, A1.z, A1.w};
            float bf[4] = {B0.x, B0.y, B0.z, B0.w};
#pragma unroll
            for (int i = 0; i < 8; i++)
#pragma unroll
                for (int j = 0; j < 4; j++) acc[i][j] = fmaf(af[i], bf[j], acc[i][j]);
        }
        __syncthreads();
    }

#pragma unroll
    for (int i = 0; i < 8; i++) {
        int gr = block_row + ty * 8 + i;
        if (gr < M) {
            float4 v = make_float4(acc[i][0], acc[i][1], acc[i][2], acc[i][3]);
            *(float4*)&g_h[(size_t)gr * C_OUT + tx * 4] = v;
        }
    }
}

// ---------------------------------------------------------------------------
// s_src[r] = g_h[r,:] . a   (warp per row)
// ---------------------------------------------------------------------------
__global__ void rowdot_kernel(const float* __restrict__ a, int M) {
    int warp = (blockIdx.x * blockDim.x + threadIdx.x) >> 5;
    int lane = threadIdx.x & 31;
    if (warp >= M) return;
    float a0 = a[lane], a1 = a[32 + lane];
    const float* h = g_h + (size_t)warp * C_OUT;
    float v = h[lane] * a0 + h[32 + lane] * a1;
#pragma unroll
    for (int o = 16; o; o >>= 1) v += __shfl_xor_sync(0xffffffffu, v, o);
    if (lane == 0) g_ssrc[warp] = v;
}

// ---------------------------------------------------------------------------
// Edge pass 1: e = leaky_relu(s_src[src]+s_dst[dst]); atomic max into g_m
// ---------------------------------------------------------------------------
__global__ void pass1_kernel(const int* __restrict__ src, const int* __restrict__ dst,
                             int E, int sdst_off) {
    int i = blockIdx.x * blockDim.x + threadIdx.x;
    if (i >= E) return;
    float e = g_ssrc[src[i]] + g_sdst[sdst_off + dst[i]];
    e = (e > 0.f) ? e : 0.2f * e;
    g_ebuf[i] = e;
    float* addr = &g_m[dst[i]];
    if (e >= 0.f)
        atomicMax((int*)addr, __float_as_int(e));
    else
        atomicMin((unsigned int*)addr, __float_as_uint(e));
}

// ---------------------------------------------------------------------------
// Edge pass 2: w = exp(e - m[dst]); atomic add into denom
// ---------------------------------------------------------------------------
__global__ void pass2_kernel(const int* __restrict__ dst, int E) {
    int i = blockIdx.x * blockDim.x + threadIdx.x;
    if (i >= E) return;
    int d = dst[i];
    float w = expf(g_ebuf[i] - g_m[d]);
    g_ebuf[i] = w;
    atomicAdd(&g_den[d], w);
}

// ---------------------------------------------------------------------------
// Edge pass 3: out[dst] += alpha * h[src]; 16 lanes per edge, float4 red.
// ---------------------------------------------------------------------------
__global__ void pass3_kernel(const int* __restrict__ src, const int* __restrict__ dst,
                             float* __restrict__ out, int E) {
    int gid = blockIdx.x * blockDim.x + threadIdx.x;
    int i = gid >> 4;
    if (i >= E) return;
    int lane = gid & 15;
    int s = src[i], d = dst[i];
    float alpha = g_ebuf[i] / (g_den[d] + 1e-16f);
    float4 h = *(const float4*)(g_h + (size_t)s * C_OUT + lane * 4);
    float* outp = out + (size_t)d * C_OUT + lane * 4;
    asm volatile("red.global.add.v4.f32 [%0], {%1, %2, %3, %4};"
                 :: "l"(outp), "f"(h.x * alpha), "f"(h.y * alpha),
                    "f"(h.z * alpha), "f"(h.w * alpha)
                 : "memory");
}

// ---------------------------------------------------------------------------
// Launch
// ---------------------------------------------------------------------------
extern "C" void kernel_launch(void* const* d_in, const int* in_sizes, int n_in,
                              void* d_out, int out_size) {
    const float* x_author = (const float*)d_in[0];
    const float* x_paper  = (const float*)d_in[1];
    const float* x_venue  = (const float*)d_in[2];

    const int* esrc[3] = {(const int*)d_in[3], (const int*)d_in[5], (const int*)d_in[7]};
    const int* edst[3] = {(const int*)d_in[4], (const int*)d_in[6], (const int*)d_in[8]};
    int Es[3] = {in_sizes[3], in_sizes[5], in_sizes[7]};

    const float* W_src[3] = {(const float*)d_in[9],  (const float*)d_in[14], (const float*)d_in[19]};
    const float* W_dst[3] = {(const float*)d_in[10], (const float*)d_in[15], (const float*)d_in[20]};
    const float* a_src[3] = {(const float*)d_in[11], (const float*)d_in[16], (const float*)d_in[21]};
    const float* a_dst[3] = {(const float*)d_in[12], (const float*)d_in[17], (const float*)d_in[22]};
    const float* bias[3]  = {(const float*)d_in[13], (const float*)d_in[18], (const float*)d_in[23]};

    const float* Xs[3] = {x_author, x_paper, x_venue};
    int Ms[3] = {in_sizes[0] / K_IN, in_sizes[1] / K_IN, in_sizes[2] / K_IN};

    float* out = (float*)d_out;

    // s_dst projection vectors + bias init + fused s_dst GEMV (shared by all types)
    compute_v_kernel<<<3, K_IN>>>(W_dst[0], a_dst[0], W_dst[1], a_dst[1], W_dst[2], a_dst[2]);
    init_out_kernel<<<(N_PAPER * C_OUT + 255) / 256, 256>>>(bias[0], bias[1], bias[2], out);
    sdst_kernel<<<(N_PAPER * 32 + 255) / 256, 256>>>(x_paper);

    for (int t = 0; t < 3; t++) {
        int M = Ms[t];
        int E = Es[t];
        gemm_kernel<<<(M + BM - 1) / BM, 256>>>(Xs[t], W_src[t], M);
        rowdot_kernel<<<(M * 32 + 255) / 256, 256>>>(a_src[t], M);
        init_md_kernel<<<(N_PAPER + 255) / 256, 256>>>();
        pass1_kernel<<<(E + 255) / 256, 256>>>(esrc[t], edst[t], E, t * N_PAPER);
        pass2_kernel<<<(E + 255) / 256, 256>>>(edst[t], E);
        long long p3_threads = (long long)E * 16;
        pass3_kernel<<<(unsigned)((p3_threads + 255) / 256), 256>>>(esrc[t], edst[t], out, E);
    }
}

// round 6
// speedup vs baseline: 1.6456x; 1.6456x over previous
#include <cuda_runtime.h>
#include <cuda_bf16.h>
#include <math.h>
#include <stdint.h>

// Problem constants (fixed by the dataset)
#define K_IN    768
#define C_OUT   64
#define N_PAPER 150000
#define E_MAX   1500000
#define NKSTEP  48          // 768 / 16
#define NNTILE  8           // 64 / 8

// ---------------------------------------------------------------------------
// Scratch (device globals; allocation is forbidden)
// ---------------------------------------------------------------------------
__device__ __align__(16) float g_h[(size_t)N_PAPER * C_OUT];   // h_src of current edge type
__device__ __align__(16) float g_ssrc[N_PAPER];                // s_src of current edge type
__device__ __align__(16) float g_sdst[3 * N_PAPER];            // s_dst for all 3 types
__device__ __align__(16) float g_m[N_PAPER];                   // per-dst running max
__device__ __align__(16) float g_den[N_PAPER];                 // per-dst softmax denom
__device__ __align__(16) float g_ebuf[E_MAX];                  // per-edge e, then w
__device__ __align__(16) float g_v[3 * K_IN];                  // W_dst @ a_dst per type
// W_src in bf16 hi/lo, pre-packed in mma.sync B-fragment order:
// [type(3)][split(2)][kstep(48)][ntile(8)][lane(32)][pair(2)] of u32
__device__ __align__(16) uint32_t g_wfrag[3 * 2 * NKSTEP * NNTILE * 32 * 2];

// ===========================================================================
// mma.sync helpers (base ISA, works on compute_103)
// ===========================================================================
__device__ __forceinline__ void mma_bf16(float* c, const uint32_t* a, const uint32_t* b) {
    asm volatile(
        "mma.sync.aligned.m16n8k16.row.col.f32.bf16.bf16.f32 "
        "{%0,%1,%2,%3}, {%4,%5,%6,%7}, {%8,%9}, {%0,%1,%2,%3};"
        : "+f"(c[0]), "+f"(c[1]), "+f"(c[2]), "+f"(c[3])
        : "r"(a[0]), "r"(a[1]), "r"(a[2]), "r"(a[3]), "r"(b[0]), "r"(b[1]));
}

__device__ __forceinline__ void ldm4(uint32_t* r, uint32_t addr) {
    asm volatile("ldmatrix.sync.aligned.m8n8.x4.shared.b16 {%0,%1,%2,%3}, [%4];"
                 : "=r"(r[0]), "=r"(r[1]), "=r"(r[2]), "=r"(r[3]) : "r"(addr));
}

__device__ __forceinline__ uint32_t smem_to_u32(const void* smem_ptr) {
    uint32_t addr;
    asm("{ .reg .u64 tmp; cvta.to.shared.u64 tmp, %1; cvt.u32.u64 %0, tmp; }"
        : "=r"(addr) : "l"(smem_ptr));
    return addr;
}

// ===========================================================================
// Small kernels
// ===========================================================================
__global__ void compute_v_kernel(const float* __restrict__ W0, const float* __restrict__ a0,
                                 const float* __restrict__ W1, const float* __restrict__ a1,
                                 const float* __restrict__ W2, const float* __restrict__ a2) {
    int t = blockIdx.x;
    const float* W = (t == 0) ? W0 : (t == 1) ? W1 : W2;
    const float* a = (t == 0) ? a0 : (t == 1) ? a1 : a2;
    int j = threadIdx.x;
    float acc = 0.f;
#pragma unroll 8
    for (int c = 0; c < C_OUT; c++) acc = fmaf(W[j * C_OUT + c], a[c], acc);
    g_v[t * K_IN + j] = acc;
}

// Pack W_src into bf16 hi/lo mma B fragments.
// B frag layout (m16n8k16 .row.col): lane l holds
//   pair0 = { B[k0+(l%4)*2, n0+l/4], B[k0+(l%4)*2+1, ...] }
//   pair1 = same at k+8.
__global__ void wfrag_kernel(const float* __restrict__ W0, const float* __restrict__ W1,
                             const float* __restrict__ W2) {
    int i = blockIdx.x * blockDim.x + threadIdx.x;
    const int N_TOT = 3 * 2 * NKSTEP * NNTILE * 32 * 2;
    if (i >= N_TOT) return;
    int p = i & 1;
    int i2 = i >> 1;
    int lane = i2 & 31;
    int i3 = i2 >> 5;
    int nt = i3 & 7;
    int i4 = i3 >> 3;
    int ks = i4 % NKSTEP;
    int i5 = i4 / NKSTEP;
    int s = i5 & 1;
    int t = i5 >> 1;
    const float* W = (t == 0) ? W0 : (t == 1) ? W1 : W2;

    int k = ks * 16 + (lane & 3) * 2 + p * 8;
    int n = nt * 8 + (lane >> 2);
    float w0 = W[k * C_OUT + n];
    float w1 = W[(k + 1) * C_OUT + n];
    __nv_bfloat16 b0, b1;
    if (s == 0) {
        b0 = __float2bfloat16(w0);
        b1 = __float2bfloat16(w1);
    } else {
        __nv_bfloat16 h0 = __float2bfloat16(w0);
        __nv_bfloat16 h1 = __float2bfloat16(w1);
        b0 = __float2bfloat16(w0 - __bfloat162float(h0));
        b1 = __float2bfloat16(w1 - __bfloat162float(h1));
    }
    uint32_t lo = (uint32_t)*reinterpret_cast<uint16_t*>(&b0);
    uint32_t hi = (uint32_t)*reinterpret_cast<uint16_t*>(&b1);
    g_wfrag[i] = lo | (hi << 16);
}

__global__ void init_out_kernel(const float* __restrict__ bw, const float* __restrict__ bc,
                                const float* __restrict__ bp, float* __restrict__ out) {
    int idx = blockIdx.x * blockDim.x + threadIdx.x;
    if (idx < N_PAPER * C_OUT) {
        int c = idx & (C_OUT - 1);
        out[idx] = bw[c] + bc[c] + bp[c];
    }
}

__global__ void init_md_kernel() {
    int idx = blockIdx.x * blockDim.x + threadIdx.x;
    if (idx < N_PAPER) {
        g_m[idx] = -INFINITY;
        g_den[idx] = 0.f;
    }
}

__global__ void sdst_kernel(const float* __restrict__ X) {
    int warp = (blockIdx.x * blockDim.x + threadIdx.x) >> 5;
    int lane = threadIdx.x & 31;
    if (warp >= N_PAPER) return;
    const float4* xr = (const float4*)(X + (size_t)warp * K_IN);
    const float4* v0 = (const float4*)(g_v);
    const float4* v1 = (const float4*)(g_v + K_IN);
    const float4* v2 = (const float4*)(g_v + 2 * K_IN);
    float a0 = 0.f, a1 = 0.f, a2 = 0.f;
#pragma unroll
    for (int i = 0; i < (K_IN / 4) / 32; i++) {
        int k = i * 32 + lane;
        float4 x = xr[k];
        float4 u;
        u = v0[k]; a0 += x.x * u.x + x.y * u.y + x.z * u.z + x.w * u.w;
        u = v1[k]; a1 += x.x * u.x + x.y * u.y + x.z * u.z + x.w * u.w;
        u = v2[k]; a2 += x.x * u.x + x.y * u.y + x.z * u.z + x.w * u.w;
    }
#pragma unroll
    for (int o = 16; o; o >>= 1) {
        a0 += __shfl_xor_sync(0xffffffffu, a0, o);
        a1 += __shfl_xor_sync(0xffffffffu, a1, o);
        a2 += __shfl_xor_sync(0xffffffffu, a2, o);
    }
    if (lane == 0) {
        g_sdst[warp] = a0;
        g_sdst[N_PAPER + warp] = a1;
        g_sdst[2 * N_PAPER + warp] = a2;
    }
}

// ===========================================================================
// HMMA GEMM: g_h[M x 64] = X[M x 768] @ W[768 x 64] via bf16 hi/lo split.
// CTA 128x64, 8 warps; warp tile 64(M) x 16(N). K chunked by 64, 12 chunks.
// A staged through smem (144B row stride, conflict-free ldmatrix);
// B loaded as pre-packed fragments straight from global (L1/L2 resident).
// ===========================================================================
#define NCHUNK 12
#define A_STRIDE 72   // bf16 elems per smem row (144 B)

__device__ __forceinline__ void split8(float4 v0, float4 v1, uint4& hi4, uint4& lo4) {
    float f[8] = {v0.x, v0.y, v0.z, v0.w, v1.x, v1.y, v1.z, v1.w};
    uint32_t hb[8], lb[8];
#pragma unroll
    for (int i = 0; i < 8; i++) {
        __nv_bfloat16 h = __float2bfloat16(f[i]);
        __nv_bfloat16 l = __float2bfloat16(f[i] - __bfloat162float(h));
        hb[i] = (uint32_t)*reinterpret_cast<uint16_t*>(&h);
        lb[i] = (uint32_t)*reinterpret_cast<uint16_t*>(&l);
    }
    hi4 = make_uint4(hb[0] | (hb[1] << 16), hb[2] | (hb[3] << 16),
                     hb[4] | (hb[5] << 16), hb[6] | (hb[7] << 16));
    lo4 = make_uint4(lb[0] | (lb[1] << 16), lb[2] | (lb[3] << 16),
                     lb[4] | (lb[5] << 16), lb[6] | (lb[7] << 16));
}

__global__ __launch_bounds__(256) void gemm_mma_kernel(
    const float* __restrict__ A,          // [M, 768] fp32
    const uint2* __restrict__ Wfrag,      // [2][48][8][32] uint2 fragments
    int M
) {
    __shared__ __align__(16) __nv_bfloat16 sA[2][128][A_STRIDE];  // [hi/lo]

    const int tid = threadIdx.x;
    const int wid = tid >> 5;
    const int lane = tid & 31;
    const int block_row = blockIdx.x * 128;

    const int warp_m = wid & 1;      // 0..1 -> rows warp_m*64
    const int warp_n = wid >> 1;     // 0..3 -> cols warp_n*16
    const int row0 = warp_m * 64;

    const uint32_t sA_hi = smem_to_u32(&sA[0][0][0]);
    const uint32_t sA_lo = smem_to_u32(&sA[1][0][0]);

    float acc[4][2][4];
#pragma unroll
    for (int a = 0; a < 4; a++)
#pragma unroll
        for (int b = 0; b < 2; b++)
#pragma unroll
            for (int c = 0; c < 4; c++) acc[a][b][c] = 0.f;

    // ldmatrix per-lane source address components (within a 16x16 A tile)
    const int lr = lane & 7;             // row within 8
    const int sel = lane >> 3;           // which 8x8 matrix
    const int lrow = lr + (sel & 1) * 8; // row offset in tile
    const int lkk = (sel >> 1) * 8;      // k offset in tile

    // Prefetch registers: 4 tasks x 8 floats
    float4 pv0[4], pv1[4];
#pragma unroll
    for (int j = 0; j < 4; j++) {
        int gi = tid + j * 256;
        int row = gi >> 3, colg = gi & 7;
        int grow = block_row + row;
        pv0[j] = make_float4(0.f, 0.f, 0.f, 0.f);
        pv1[j] = pv0[j];
        if (grow < M) {
            const float4* p = (const float4*)(A + (size_t)grow * K_IN + colg * 8);
            pv0[j] = p[0];
            pv1[j] = p[1];
        }
    }

    for (int c = 0; c < NCHUNK; c++) {
        __syncthreads();   // previous chunk's ldmatrix reads are done
        // store prefetched A chunk to smem (split hi/lo)
#pragma unroll
        for (int j = 0; j < 4; j++) {
            int gi = tid + j * 256;
            int row = gi >> 3, colg = gi & 7;
            uint4 h4, l4;
            split8(pv0[j], pv1[j], h4, l4);
            *(uint4*)&sA[0][row][colg * 8] = h4;
            *(uint4*)&sA[1][row][colg * 8] = l4;
        }
        __syncthreads();

        // prefetch next chunk
        if (c + 1 < NCHUNK) {
#pragma unroll
            for (int j = 0; j < 4; j++) {
                int gi = tid + j * 256;
                int row = gi >> 3, colg = gi & 7;
                int grow = block_row + row;
                pv0[j] = make_float4(0.f, 0.f, 0.f, 0.f);
                pv1[j] = pv0[j];
                if (grow < M) {
                    const float4* p =
                        (const float4*)(A + (size_t)grow * K_IN + (c + 1) * 64 + colg * 8);
                    pv0[j] = p[0];
                    pv1[j] = p[1];
                }
            }
        }

        // compute on current chunk: 4 k-steps of 16
#pragma unroll
        for (int ks = 0; ks < 4; ks++) {
            const int ksg = c * 4 + ks;
            // A fragments (hi & lo) for 4 m-tiles
            uint32_t ah[4][4], al[4][4];
#pragma unroll
            for (int mt = 0; mt < 4; mt++) {
                uint32_t off = (uint32_t)((row0 + mt * 16 + lrow) * A_STRIDE
                                          + ks * 16 + lkk) * 2u;
                ldm4(ah[mt], sA_hi + off);
                ldm4(al[mt], sA_lo + off);
            }
            // B fragments: 2 n-tiles x {hi, lo}
            uint32_t bh[2][2], bl[2][2];
#pragma unroll
            for (int nt2 = 0; nt2 < 2; nt2++) {
                int nt = warp_n * 2 + nt2;
                uint2 vh = Wfrag[((0 * NKSTEP + ksg) * NNTILE + nt) * 32 + lane];
                uint2 vl = Wfrag[((1 * NKSTEP + ksg) * NNTILE + nt) * 32 + lane];
                bh[nt2][0] = vh.x; bh[nt2][1] = vh.y;
                bl[nt2][0] = vl.x; bl[nt2][1] = vl.y;
            }
            // MMAs: hi*hi + hi*lo + lo*hi
#pragma unroll
            for (int mt = 0; mt < 4; mt++)
#pragma unroll
                for (int nt2 = 0; nt2 < 2; nt2++) {
                    mma_bf16(acc[mt][nt2], ah[mt], bh[nt2]);
                    mma_bf16(acc[mt][nt2], ah[mt], bl[nt2]);
                    mma_bf16(acc[mt][nt2], al[mt], bh[nt2]);
                }
        }
    }

    // Epilogue: write h. Fragment C layout: c0 at (row=lane/4, col=(lane%4)*2).
    const int erow = lane >> 2;
    const int ecol = (lane & 3) * 2;
#pragma unroll
    for (int mt = 0; mt < 4; mt++) {
#pragma unroll
        for (int nt2 = 0; nt2 < 2; nt2++) {
            int col = warp_n * 16 + nt2 * 8 + ecol;
            int ra = block_row + row0 + mt * 16 + erow;
            int rb = ra + 8;
            if (ra < M)
                *(float2*)&g_h[(size_t)ra * C_OUT + col] =
                    make_float2(acc[mt][nt2][0], acc[mt][nt2][1]);
            if (rb < M)
                *(float2*)&g_h[(size_t)rb * C_OUT + col] =
                    make_float2(acc[mt][nt2][2], acc[mt][nt2][3]);
        }
    }
}

// ---------------------------------------------------------------------------
// s_src[r] = g_h[r,:] . a   (warp per row)
// ---------------------------------------------------------------------------
__global__ void rowdot_kernel(const float* __restrict__ a, int M) {
    int warp = (blockIdx.x * blockDim.x + threadIdx.x) >> 5;
    int lane = threadIdx.x & 31;
    if (warp >= M) return;
    float a0 = a[lane], a1 = a[32 + lane];
    const float* h = g_h + (size_t)warp * C_OUT;
    float v = h[lane] * a0 + h[32 + lane] * a1;
#pragma unroll
    for (int o = 16; o; o >>= 1) v += __shfl_xor_sync(0xffffffffu, v, o);
    if (lane == 0) g_ssrc[warp] = v;
}

// ===========================================================================
// Edge passes
// ===========================================================================
__global__ void pass1_kernel(const int* __restrict__ src, const int* __restrict__ dst,
                             int E, int sdst_off) {
    int i = blockIdx.x * blockDim.x + threadIdx.x;
    if (i >= E) return;
    float e = g_ssrc[src[i]] + g_sdst[sdst_off + dst[i]];
    e = (e > 0.f) ? e : 0.2f * e;
    g_ebuf[i] = e;
    float* addr = &g_m[dst[i]];
    if (e >= 0.f)
        atomicMax((int*)addr, __float_as_int(e));
    else
        atomicMin((unsigned int*)addr, __float_as_uint(e));
}

__global__ void pass2_kernel(const int* __restrict__ dst, int E) {
    int i = blockIdx.x * blockDim.x + threadIdx.x;
    if (i >= E) return;
    int d = dst[i];
    float w = expf(g_ebuf[i] - g_m[d]);
    g_ebuf[i] = w;
    atomicAdd(&g_den[d], w);
}

__global__ void pass3_kernel(const int* __restrict__ src, const int* __restrict__ dst,
                             float* __restrict__ out, int E) {
    int gid = blockIdx.x * blockDim.x + threadIdx.x;
    int i = gid >> 4;
    if (i >= E) return;
    int lane = gid & 15;
    int s = src[i], d = dst[i];
    float alpha = g_ebuf[i] / (g_den[d] + 1e-16f);
    float4 h = *(const float4*)(g_h + (size_t)s * C_OUT + lane * 4);
    float* outp = out + (size_t)d * C_OUT + lane * 4;
    asm volatile("red.global.add.v4.f32 [%0], {%1, %2, %3, %4};"
                 :: "l"(outp), "f"(h.x * alpha), "f"(h.y * alpha),
                    "f"(h.z * alpha), "f"(h.w * alpha)
                 : "memory");
}

// ===========================================================================
// Launch
// ===========================================================================
extern "C" void kernel_launch(void* const* d_in, const int* in_sizes, int n_in,
                              void* d_out, int out_size) {
    const float* x_author = (const float*)d_in[0];
    const float* x_paper  = (const float*)d_in[1];
    const float* x_venue  = (const float*)d_in[2];

    const int* esrc[3] = {(const int*)d_in[3], (const int*)d_in[5], (const int*)d_in[7]};
    const int* edst[3] = {(const int*)d_in[4], (const int*)d_in[6], (const int*)d_in[8]};
    int Es[3] = {in_sizes[3], in_sizes[5], in_sizes[7]};

    const float* W_src[3] = {(const float*)d_in[9],  (const float*)d_in[14], (const float*)d_in[19]};
    const float* W_dst[3] = {(const float*)d_in[10], (const float*)d_in[15], (const float*)d_in[20]};
    const float* a_src[3] = {(const float*)d_in[11], (const float*)d_in[16], (const float*)d_in[21]};
    const float* a_dst[3] = {(const float*)d_in[12], (const float*)d_in[17], (const float*)d_in[22]};
    const float* bias[3]  = {(const float*)d_in[13], (const float*)d_in[18], (const float*)d_in[23]};

    const float* Xs[3] = {x_author, x_paper, x_venue};
    int Ms[3] = {in_sizes[0] / K_IN, in_sizes[1] / K_IN, in_sizes[2] / K_IN};

    float* out = (float*)d_out;

    // Shared prep
    compute_v_kernel<<<3, K_IN>>>(W_dst[0], a_dst[0], W_dst[1], a_dst[1], W_dst[2], a_dst[2]);
    {
        const int N_TOT = 3 * 2 * NKSTEP * NNTILE * 32 * 2;
        wfrag_kernel<<<(N_TOT + 255) / 256, 256>>>(W_src[0], W_src[1], W_src[2]);
    }
    init_out_kernel<<<(N_PAPER * C_OUT + 255) / 256, 256>>>(bias[0], bias[1], bias[2], out);
    sdst_kernel<<<(N_PAPER * 32 + 255) / 256, 256>>>(x_paper);

    uint32_t* wf_dev;
    cudaGetSymbolAddress((void**)&wf_dev, g_wfrag);

    for (int t = 0; t < 3; t++) {
        int M = Ms[t];
        int E = Es[t];
        const uint2* Wf = (const uint2*)(wf_dev + (size_t)t * 2 * NKSTEP * NNTILE * 32 * 2);
        gemm_mma_kernel<<<(M + 127) / 128, 256>>>(Xs[t], Wf, M);
        rowdot_kernel<<<(M * 32 + 255) / 256, 256>>>(a_src[t], M);
        init_md_kernel<<<(N_PAPER + 255) / 256, 256>>>();
        pass1_kernel<<<(E + 255) / 256, 256>>>(esrc[t], edst[t], E, t * N_PAPER);
        pass2_kernel<<<(E + 255) / 256, 256>>>(edst[t], E);
        long long p3_threads = (long long)E * 16;
        pass3_kernel<<<(unsigned)((p3_threads + 255) / 256), 256>>>(esrc[t], edst[t], out, E);
    }
}